// round 13
// baseline (speedup 1.0000x reference)
#include <cuda_runtime.h>
#include <math.h>
#include <stdint.h>

#define BB 2
#define SS 2048
#define DD 1024
#define HH 16
#define HD 64

// -------- scratch (allocation-free: __device__ globals) --------
__device__ float g_Q[BB*SS*DD];
__device__ float g_K[BB*SS*DD];
__device__ float g_V[BB*SS*DD];
__device__ float g_att[BB*SS*DD];
// tf32-rounded copies of inputs/weights (feed cvt-free GEMM inner loops)
__device__ float g_qc[BB*SS*DD];
__device__ float g_kc[BB*SS*DD];
__device__ float g_vc[BB*SS*DD];
__device__ float g_Wqc[DD*DD];
__device__ float g_Wkc[DD*DD];
__device__ float g_Wvc[DD*DD];
__device__ float g_Woc[DD*DD];

// -------- helpers --------
__device__ __forceinline__ uint32_t f2tf32(float x) {
    uint32_t r;
    asm("cvt.rna.tf32.f32 %0, %1;" : "=r"(r) : "f"(x));
    return r;
}

__device__ __forceinline__ void mma_tf32(float* d, const uint32_t* a, const uint32_t* b) {
    asm volatile(
        "mma.sync.aligned.m16n8k8.row.col.f32.tf32.tf32.f32 "
        "{%0,%1,%2,%3},{%4,%5,%6,%7},{%8,%9},{%0,%1,%2,%3};"
        : "+f"(d[0]), "+f"(d[1]), "+f"(d[2]), "+f"(d[3])
        : "r"(a[0]), "r"(a[1]), "r"(a[2]), "r"(a[3]), "r"(b[0]), "r"(b[1]));
}

__device__ __forceinline__ void cp_async16(uint32_t smem_addr, const void* gptr) {
    asm volatile("cp.async.cg.shared.global [%0], [%1], 16;"
                 :: "r"(smem_addr), "l"(gptr));
}
__device__ __forceinline__ void cp_commit() {
    asm volatile("cp.async.commit_group;");
}
template <int N>
__device__ __forceinline__ void cp_wait() {
    asm volatile("cp.async.wait_group %0;" :: "n"(N));
}

// ======================================================================
// Elementwise tf32 rounding pass (once per launch on inputs/weights)
// ======================================================================
__global__ __launch_bounds__(256) void cvt_tf32_kernel(
    const float* __restrict__ in, float* __restrict__ out, int n4)
{
    int i = blockIdx.x * blockDim.x + threadIdx.x;
    if (i < n4) {
        float4 v = ((const float4*)in)[i];
        uint4 u = { f2tf32(v.x), f2tf32(v.y), f2tf32(v.z), f2tf32(v.w) };
        ((uint4*)out)[i] = u;
    }
}

// ======================================================================
// GEMM v7: C = A * Bw^T (+bias), tf32 mma.sync, NO cvt in inner loop
// (A and Bw must be pre-rounded to tf32 values).
// block 128M x 128N, 256 threads (8 warps, 4Mx2N), warp tile 32x64, KT=32
// 2-stage cp.async; 2 CTAs/SM. round_out rounds scratch outputs.
// smem: 2 x (128x36 + 128x36) floats = 73,728 B
// ======================================================================
#define G_SMEM_BYTES ((2*128*36 + 2*128*36) * 4)

__device__ __forceinline__ void gemm_body(
    const float* __restrict__ A, const float* __restrict__ Bw,
    const float* __restrict__ bias, float* __restrict__ C, int round_out)
{
    extern __shared__ float gsm[];
    float* As = gsm;                 // [2][128*36]
    float* Bs = gsm + 2 * 128 * 36;  // [2][128*36]

    const int tid  = threadIdx.x;
    const int lane = tid & 31;
    const int w    = tid >> 5;
    const int wm   = w & 3;        // 0..3 -> 32 rows each
    const int wn   = w >> 2;       // 0..1 -> 64 cols each
    const int lr   = lane >> 2;
    const int lc   = lane & 3;

    const int m0 = blockIdx.y * 128;
    const int n0 = blockIdx.x * 128;
    const int K = 1024, N = 1024;

    const uint32_t as_base = (uint32_t)__cvta_generic_to_shared(As);
    const uint32_t bs_base = (uint32_t)__cvta_generic_to_shared(Bs);

    auto load_stage = [&](int s, int kt) {
        #pragma unroll
        for (int i = 0; i < 4; i++) {
            int id = tid + i * 256;
            int r = id >> 3, c = (id & 7) * 4;
            cp_async16(as_base + (s * 128 * 36 + r * 36 + c) * 4,
                       &A[(size_t)(m0 + r) * K + kt + c]);
            cp_async16(bs_base + (s * 128 * 36 + r * 36 + c) * 4,
                       &Bw[(size_t)(n0 + r) * K + kt + c]);
        }
        cp_commit();
    };

    float acc[2][8][4];
    #pragma unroll
    for (int i = 0; i < 2; i++)
        #pragma unroll
        for (int j = 0; j < 8; j++)
            #pragma unroll
            for (int t = 0; t < 4; t++) acc[i][j][t] = 0.0f;

    load_stage(0, 0);

    int st = 0;
    for (int kt = 0; kt < K; kt += 32, st ^= 1) {
        if (kt + 32 < K) { load_stage(st ^ 1, kt + 32); cp_wait<1>(); }
        else             { cp_wait<0>(); }
        __syncthreads();

        const uint32_t* Ac = (const uint32_t*)(As + st * 128 * 36);
        const uint32_t* Bc = (const uint32_t*)(Bs + st * 128 * 36);

        #pragma unroll
        for (int ks = 0; ks < 4; ks++) {
            const int kk = ks * 8;
            uint32_t af[2][4];
            #pragma unroll
            for (int mf = 0; mf < 2; mf++) {
                int r = wm * 32 + mf * 16 + lr;
                af[mf][0] = Ac[r * 36 + kk + lc];
                af[mf][1] = Ac[(r + 8) * 36 + kk + lc];
                af[mf][2] = Ac[r * 36 + kk + lc + 4];
                af[mf][3] = Ac[(r + 8) * 36 + kk + lc + 4];
            }
            uint32_t bf[8][2];
            #pragma unroll
            for (int nf = 0; nf < 8; nf++) {
                int n = wn * 64 + nf * 8 + lr;
                bf[nf][0] = Bc[n * 36 + kk + lc];
                bf[nf][1] = Bc[n * 36 + kk + lc + 4];
            }
            #pragma unroll
            for (int mf = 0; mf < 2; mf++)
                #pragma unroll
                for (int nf = 0; nf < 8; nf++)
                    mma_tf32(acc[mf][nf], af[mf], bf[nf]);
        }
        __syncthreads();
    }

    #pragma unroll
    for (int mf = 0; mf < 2; mf++) {
        int r = m0 + wm * 32 + mf * 16 + lr;
        #pragma unroll
        for (int nf = 0; nf < 8; nf++) {
            int c = n0 + wn * 64 + nf * 8 + 2 * lc;
            float b0 = 0.0f, b1 = 0.0f;
            if (bias) { b0 = bias[c]; b1 = bias[c + 1]; }
            float o00 = acc[mf][nf][0] + b0, o01 = acc[mf][nf][1] + b1;
            float o10 = acc[mf][nf][2] + b0, o11 = acc[mf][nf][3] + b1;
            if (round_out) {
                o00 = __uint_as_float(f2tf32(o00)); o01 = __uint_as_float(f2tf32(o01));
                o10 = __uint_as_float(f2tf32(o10)); o11 = __uint_as_float(f2tf32(o11));
            }
            float2 v0 = { o00, o01 };
            float2 v1 = { o10, o11 };
            *(float2*)&C[(size_t)r * N + c] = v0;
            *(float2*)&C[(size_t)(r + 8) * N + c] = v1;
        }
    }
}

__global__ __launch_bounds__(256, 2) void gemm_qkv(
    const float* __restrict__ Xq, const float* __restrict__ Xk,
    const float* __restrict__ Xv,
    const float* __restrict__ Wq, const float* __restrict__ Wk,
    const float* __restrict__ Wv,
    float* __restrict__ Oq, float* __restrict__ Ok, float* __restrict__ Ov)
{
    const int z = blockIdx.z;
    const float* A  = (z == 0) ? Xq : (z == 1) ? Xk : Xv;
    const float* Bw = (z == 0) ? Wq : (z == 1) ? Wk : Wv;
    float*       C  = (z == 0) ? Oq : (z == 1) ? Ok : Ov;
    gemm_body(A, Bw, nullptr, C, 1);
}

__global__ __launch_bounds__(256, 2) void gemm_out(
    const float* __restrict__ A, const float* __restrict__ Bw,
    const float* __restrict__ bias, float* __restrict__ C)
{
    gemm_body(A, Bw, bias, C, 0);
}

// ======================================================================
// Flash attention v4 (R9/R12-proven): 128-q tile, 4 warps (32q each),
// 64-key tiles, register prefetch, warp-local softmax, stride 68.
// Inputs pre-rounded tf32 by gemm epilogue -> no cvt on Q/K/V.
// Output tf32-rounded so out-gemm can skip cvt too.
// layout (floats): qs 128x68 @0, ks 64x68 @8704, vs @13056, ps 128x68 @17408
// total 26112 floats = 104,448 B
// ======================================================================
#define FL_STR 68
#define FL_SMEM_BYTES (26112 * 4)

__global__ __launch_bounds__(128) void flash_tf32_v4(
    const float* __restrict__ Q, const float* __restrict__ Kp,
    const float* __restrict__ Vp, float* __restrict__ O)
{
    extern __shared__ float smf[];
    uint32_t* qs = (uint32_t*)smf;
    uint32_t* ks = (uint32_t*)(smf + 8704);
    uint32_t* vs = (uint32_t*)(smf + 13056);
    uint32_t* ps = (uint32_t*)(smf + 17408);

    const int tid  = threadIdx.x;
    const int lane = tid & 31;
    const int w    = tid >> 5;
    const int lr   = lane >> 2;
    const int lc   = lane & 3;

    const int bh = blockIdx.y;
    const int b  = bh >> 4;
    const int h  = bh & 15;
    const int q0 = blockIdx.x * 128;
    const float scale = 0.03125f;   // 2^-5 exact

    const int fr = tid >> 4;
    const int fc = (tid & 15) * 4;

    const float* qbase = Q + ((size_t)(b * SS + q0)) * DD + h * HD;
    #pragma unroll
    for (int i = 0; i < 16; i++) {
        int r = fr + i * 8;
        float4 v = *(const float4*)&qbase[(size_t)r * DD + fc];
        uint4 u = { __float_as_uint(v.x * scale), __float_as_uint(v.y * scale),
                    __float_as_uint(v.z * scale), __float_as_uint(v.w * scale) };
        *(uint4*)&qs[r * FL_STR + fc] = u;
    }

    float m_state[2][2], l_state[2][2];
    float acco[2][8][4];
    #pragma unroll
    for (int mf = 0; mf < 2; mf++)
        #pragma unroll
        for (int hh = 0; hh < 2; hh++) { m_state[mf][hh] = -INFINITY; l_state[mf][hh] = 0.0f; }
    #pragma unroll
    for (int mf = 0; mf < 2; mf++)
        #pragma unroll
        for (int nf = 0; nf < 8; nf++)
            #pragma unroll
            for (int t = 0; t < 4; t++) acco[mf][nf][t] = 0.0f;

    const float* kb0 = Kp + ((size_t)(b * SS)) * DD + h * HD;
    const float* vb0 = Vp + ((size_t)(b * SS)) * DD + h * HD;
    float4 kreg[8], vreg[8];
    #pragma unroll
    for (int i = 0; i < 8; i++) {
        int r = fr + i * 8;
        kreg[i] = *(const float4*)&kb0[(size_t)r * DD + fc];
        vreg[i] = *(const float4*)&vb0[(size_t)r * DD + fc];
    }

    for (int kb = 0; kb < SS / 64; kb++) {
        __syncthreads();
        #pragma unroll
        for (int i = 0; i < 8; i++) {
            int r = fr + i * 8;
            uint4 uk = { __float_as_uint(kreg[i].x), __float_as_uint(kreg[i].y),
                         __float_as_uint(kreg[i].z), __float_as_uint(kreg[i].w) };
            uint4 uv = { __float_as_uint(vreg[i].x), __float_as_uint(vreg[i].y),
                         __float_as_uint(vreg[i].z), __float_as_uint(vreg[i].w) };
            *(uint4*)&ks[r * FL_STR + fc] = uk;
            *(uint4*)&vs[r * FL_STR + fc] = uv;
        }
        __syncthreads();

        if (kb + 1 < SS / 64) {
            const float* kbn = Kp + ((size_t)(b * SS + (kb + 1) * 64)) * DD + h * HD;
            const float* vbn = Vp + ((size_t)(b * SS + (kb + 1) * 64)) * DD + h * HD;
            #pragma unroll
            for (int i = 0; i < 8; i++) {
                int r = fr + i * 8;
                kreg[i] = *(const float4*)&kbn[(size_t)r * DD + fc];
                vreg[i] = *(const float4*)&vbn[(size_t)r * DD + fc];
            }
        }

        float accs[2][8][4];
        #pragma unroll
        for (int mf = 0; mf < 2; mf++)
            #pragma unroll
            for (int nf = 0; nf < 8; nf++)
                #pragma unroll
                for (int t = 0; t < 4; t++) accs[mf][nf][t] = 0.0f;

        #pragma unroll
        for (int ksi = 0; ksi < 8; ksi++) {
            const int kk = ksi * 8;
            uint32_t af[2][4];
            #pragma unroll
            for (int mf = 0; mf < 2; mf++) {
                int r = w * 32 + mf * 16 + lr;
                af[mf][0] = qs[r * FL_STR + kk + lc];
                af[mf][1] = qs[(r + 8) * FL_STR + kk + lc];
                af[mf][2] = qs[r * FL_STR + kk + lc + 4];
                af[mf][3] = qs[(r + 8) * FL_STR + kk + lc + 4];
            }
            uint32_t bf[8][2];
            #pragma unroll
            for (int nf = 0; nf < 8; nf++) {
                int n = nf * 8 + lr;
                bf[nf][0] = ks[n * FL_STR + kk + lc];
                bf[nf][1] = ks[n * FL_STR + kk + lc + 4];
            }
            #pragma unroll
            for (int mf = 0; mf < 2; mf++)
                #pragma unroll
                for (int nf = 0; nf < 8; nf++)
                    mma_tf32(accs[mf][nf], af[mf], bf[nf]);
        }

        float cc[2][2];
        #pragma unroll
        for (int mf = 0; mf < 2; mf++)
            #pragma unroll
            for (int hh = 0; hh < 2; hh++) {
                float v = -INFINITY;
                #pragma unroll
                for (int nf = 0; nf < 8; nf++) {
                    v = fmaxf(v, accs[mf][nf][2 * hh]);
                    v = fmaxf(v, accs[mf][nf][2 * hh + 1]);
                }
                v = fmaxf(v, __shfl_xor_sync(0xffffffffu, v, 1));
                v = fmaxf(v, __shfl_xor_sync(0xffffffffu, v, 2));
                float mnew = fmaxf(m_state[mf][hh], v);
                cc[mf][hh] = __expf(m_state[mf][hh] - mnew);
                m_state[mf][hh] = mnew;
            }

        float rsum[2][2] = {};
        #pragma unroll
        for (int mf = 0; mf < 2; mf++) {
            #pragma unroll
            for (int nf = 0; nf < 8; nf++) {
                float p0 = __expf(accs[mf][nf][0] - m_state[mf][0]);
                float p1 = __expf(accs[mf][nf][1] - m_state[mf][0]);
                float p2 = __expf(accs[mf][nf][2] - m_state[mf][1]);
                float p3 = __expf(accs[mf][nf][3] - m_state[mf][1]);
                rsum[mf][0] += p0 + p1;
                rsum[mf][1] += p2 + p3;
                int r = w * 32 + mf * 16 + lr;
                int c = nf * 8 + 2 * lc;
                uint2 u0 = { f2tf32(p0), f2tf32(p1) };
                uint2 u1 = { f2tf32(p2), f2tf32(p3) };
                *(uint2*)&ps[r * FL_STR + c] = u0;
                *(uint2*)&ps[(r + 8) * FL_STR + c] = u1;
            }
        }
        #pragma unroll
        for (int mf = 0; mf < 2; mf++)
            #pragma unroll
            for (int hh = 0; hh < 2; hh++) {
                float v = rsum[mf][hh];
                v += __shfl_xor_sync(0xffffffffu, v, 1);
                v += __shfl_xor_sync(0xffffffffu, v, 2);
                l_state[mf][hh] = l_state[mf][hh] * cc[mf][hh] + v;
            }

        #pragma unroll
        for (int mf = 0; mf < 2; mf++)
            #pragma unroll
            for (int nf = 0; nf < 8; nf++) {
                acco[mf][nf][0] *= cc[mf][0];
                acco[mf][nf][1] *= cc[mf][0];
                acco[mf][nf][2] *= cc[mf][1];
                acco[mf][nf][3] *= cc[mf][1];
            }

        __syncwarp();

        #pragma unroll
        for (int ksi = 0; ksi < 8; ksi++) {
            const int kk = ksi * 8;
            uint32_t af[2][4];
            #pragma unroll
            for (int mf = 0; mf < 2; mf++) {
                int r = w * 32 + mf * 16 + lr;
                af[mf][0] = ps[r * FL_STR + kk + lc];
                af[mf][1] = ps[(r + 8) * FL_STR + kk + lc];
                af[mf][2] = ps[r * FL_STR + kk + lc + 4];
                af[mf][3] = ps[(r + 8) * FL_STR + kk + lc + 4];
            }
            uint32_t bf[8][2];
            #pragma unroll
            for (int nf = 0; nf < 8; nf++) {
                int n = nf * 8 + lr;
                bf[nf][0] = vs[(kk + lc) * FL_STR + n];
                bf[nf][1] = vs[(kk + lc + 4) * FL_STR + n];
            }
            #pragma unroll
            for (int mf = 0; mf < 2; mf++)
                #pragma unroll
                for (int nf = 0; nf < 8; nf++)
                    mma_tf32(acco[mf][nf], af[mf], bf[nf]);
        }
    }

    // epilogue: normalize + tf32-round (out-gemm reads raw bits)
    float* obase = O + ((size_t)(b * SS + q0)) * DD + h * HD;
    #pragma unroll
    for (int mf = 0; mf < 2; mf++) {
        float inv0 = 1.0f / l_state[mf][0];
        float inv1 = 1.0f / l_state[mf][1];
        int r = w * 32 + mf * 16 + lr;
        #pragma unroll
        for (int nf = 0; nf < 8; nf++) {
            int c = nf * 8 + 2 * lc;
            uint2 v0 = { f2tf32(acco[mf][nf][0] * inv0), f2tf32(acco[mf][nf][1] * inv0) };
            uint2 v1 = { f2tf32(acco[mf][nf][2] * inv1), f2tf32(acco[mf][nf][3] * inv1) };
            *(uint2*)&obase[(size_t)r * DD + c] = v0;
            *(uint2*)&obase[(size_t)(r + 8) * DD + c] = v1;
        }
    }
}

// ======================================================================
// launch
// ======================================================================
extern "C" void kernel_launch(void* const* d_in, const int* in_sizes, int n_in,
                              void* d_out, int out_size)
{
    const float* queries = (const float*)d_in[0];
    const float* keys    = (const float*)d_in[1];
    const float* values  = (const float*)d_in[2];
    const float* Wq      = (const float*)d_in[3];
    const float* Wk      = (const float*)d_in[4];
    const float* Wv      = (const float*)d_in[5];
    const float* Wo      = (const float*)d_in[6];
    const float* bo      = (const float*)d_in[7];
    float* out = (float*)d_out;

    float *gQ, *gK, *gV, *gA, *gqc, *gkc, *gvc, *gwq, *gwk, *gwv, *gwo;
    cudaGetSymbolAddress((void**)&gQ, g_Q);
    cudaGetSymbolAddress((void**)&gK, g_K);
    cudaGetSymbolAddress((void**)&gV, g_V);
    cudaGetSymbolAddress((void**)&gA, g_att);
    cudaGetSymbolAddress((void**)&gqc, g_qc);
    cudaGetSymbolAddress((void**)&gkc, g_kc);
    cudaGetSymbolAddress((void**)&gvc, g_vc);
    cudaGetSymbolAddress((void**)&gwq, g_Wqc);
    cudaGetSymbolAddress((void**)&gwk, g_Wkc);
    cudaGetSymbolAddress((void**)&gwv, g_Wvc);
    cudaGetSymbolAddress((void**)&gwo, g_Woc);

    cudaFuncSetAttribute(gemm_qkv,
                         cudaFuncAttributeMaxDynamicSharedMemorySize, G_SMEM_BYTES);
    cudaFuncSetAttribute(gemm_out,
                         cudaFuncAttributeMaxDynamicSharedMemorySize, G_SMEM_BYTES);
    cudaFuncSetAttribute(flash_tf32_v4,
                         cudaFuncAttributeMaxDynamicSharedMemorySize, FL_SMEM_BYTES);

    const int NELEM = BB * SS * DD;       // 4M
    const int WELEM = DD * DD;            // 1M

    // tf32-round inputs + weights once (enables cvt-free GEMM loops)
    cvt_tf32_kernel<<<NELEM / 1024, 256>>>(queries, gqc, NELEM / 4);
    cvt_tf32_kernel<<<NELEM / 1024, 256>>>(keys,    gkc, NELEM / 4);
    cvt_tf32_kernel<<<NELEM / 1024, 256>>>(values,  gvc, NELEM / 4);
    cvt_tf32_kernel<<<WELEM / 1024, 256>>>(Wq, gwq, WELEM / 4);
    cvt_tf32_kernel<<<WELEM / 1024, 256>>>(Wk, gwk, WELEM / 4);
    cvt_tf32_kernel<<<WELEM / 1024, 256>>>(Wv, gwv, WELEM / 4);
    cvt_tf32_kernel<<<WELEM / 1024, 256>>>(Wo, gwo, WELEM / 4);

    dim3 qkv_grid(8, 32, 3);   // 768 CTAs (128x128 tiles)
    dim3 gemm_block(256);
    gemm_qkv<<<qkv_grid, gemm_block, G_SMEM_BYTES>>>(
        gqc, gkc, gvc, gwq, gwk, gwv, gQ, gK, gV);

    dim3 fl_grid(SS / 128, BB * HH);   // 512 CTAs
    flash_tf32_v4<<<fl_grid, 128, FL_SMEM_BYTES>>>(gQ, gK, gV, gA);

    dim3 out_grid(8, 32, 1);
    gemm_out<<<out_grid, gemm_block, G_SMEM_BYTES>>>(gA, gwo, bo, out);
}

// round 14
// speedup vs baseline: 1.6252x; 1.6252x over previous
#include <cuda_runtime.h>
#include <cuda_fp16.h>
#include <math.h>
#include <stdint.h>

#define BB 2
#define SS 2048
#define DD 1024
#define HH 16
#define HD 64

// -------- scratch (allocation-free: __device__ globals) --------
__device__ __half g_qh[BB*SS*DD];
__device__ __half g_kh[BB*SS*DD];
__device__ __half g_vh[BB*SS*DD];
__device__ __half g_wqh[DD*DD];
__device__ __half g_wkh[DD*DD];
__device__ __half g_wvh[DD*DD];
__device__ __half g_woh[DD*DD];
__device__ __half g_Qp[BB*SS*DD];
__device__ __half g_Kp[BB*SS*DD];
__device__ __half g_Vp[BB*SS*DD];
__device__ __half g_Ah[BB*SS*DD];

// -------- helpers --------
__device__ __forceinline__ void mma_f16(float* d, const uint32_t* a, const uint32_t* b) {
    asm volatile(
        "mma.sync.aligned.m16n8k16.row.col.f32.f16.f16.f32 "
        "{%0,%1,%2,%3},{%4,%5,%6,%7},{%8,%9},{%0,%1,%2,%3};"
        : "+f"(d[0]), "+f"(d[1]), "+f"(d[2]), "+f"(d[3])
        : "r"(a[0]), "r"(a[1]), "r"(a[2]), "r"(a[3]), "r"(b[0]), "r"(b[1]));
}

__device__ __forceinline__ uint32_t packh2(float a, float b) {
    __half2 h = __floats2half2_rn(a, b);
    return *(uint32_t*)&h;
}

__device__ __forceinline__ void cp_async16(uint32_t smem_addr, const void* gptr) {
    asm volatile("cp.async.cg.shared.global [%0], [%1], 16;"
                 :: "r"(smem_addr), "l"(gptr));
}
__device__ __forceinline__ void cp_commit() {
    asm volatile("cp.async.commit_group;");
}
template <int N>
__device__ __forceinline__ void cp_wait() {
    asm volatile("cp.async.wait_group %0;" :: "n"(N));
}

// ======================================================================
// fp32 -> fp16 conversion passes (fused: 3 inputs / 4 weights via grid.z)
// ======================================================================
__global__ __launch_bounds__(256) void cvt_in3(
    const float* __restrict__ a, const float* __restrict__ b, const float* __restrict__ c,
    __half* __restrict__ oa, __half* __restrict__ ob, __half* __restrict__ oc, int n4)
{
    const float* in = (blockIdx.z == 0) ? a : (blockIdx.z == 1) ? b : c;
    __half* out     = (blockIdx.z == 0) ? oa : (blockIdx.z == 1) ? ob : oc;
    int i = blockIdx.x * blockDim.x + threadIdx.x;
    if (i < n4) {
        float4 v = ((const float4*)in)[i];
        uint2 u = { packh2(v.x, v.y), packh2(v.z, v.w) };
        ((uint2*)out)[i] = u;
    }
}

__global__ __launch_bounds__(256) void cvt_w4(
    const float* __restrict__ a, const float* __restrict__ b,
    const float* __restrict__ c, const float* __restrict__ d,
    __half* __restrict__ oa, __half* __restrict__ ob,
    __half* __restrict__ oc, __half* __restrict__ od, int n4)
{
    const float* in = (blockIdx.z == 0) ? a : (blockIdx.z == 1) ? b : (blockIdx.z == 2) ? c : d;
    __half* out     = (blockIdx.z == 0) ? oa : (blockIdx.z == 1) ? ob : (blockIdx.z == 2) ? oc : od;
    int i = blockIdx.x * blockDim.x + threadIdx.x;
    if (i < n4) {
        float4 v = ((const float4*)in)[i];
        uint2 u = { packh2(v.x, v.y), packh2(v.z, v.w) };
        ((uint2*)out)[i] = u;
    }
}

// ======================================================================
// GEMM fp16: C[M,1024] = A[M,1024] * Bw[1024,1024]^T (+bias)
// A,Bw fp16 (K-major). block 128M x 128N, 256 thr (8 warps, 4Mx2N),
// warp tile 32x64, K-tile 64 halves, 2-stage cp.async.
// smem: 2 x (128x36 + 128x36) uint32 = 73,728 B. m16n8k16, f32 accum.
// ======================================================================
#define G_SMEM_BYTES ((2*128*36 + 2*128*36) * 4)

__device__ __forceinline__ void gemm_body_f16(
    const __half* __restrict__ A, const __half* __restrict__ Bw,
    const float* __restrict__ bias, void* Cout, int half_out)
{
    extern __shared__ uint32_t gsm[];
    uint32_t* As = gsm;                 // [2][128*36]
    uint32_t* Bs = gsm + 2 * 128 * 36;  // [2][128*36]

    const int tid  = threadIdx.x;
    const int lane = tid & 31;
    const int w    = tid >> 5;
    const int wm   = w & 3;        // 0..3 -> 32 rows
    const int wn   = w >> 2;       // 0..1 -> 64 cols
    const int lr   = lane >> 2;
    const int lc   = lane & 3;

    const int m0 = blockIdx.y * 128;
    const int n0 = blockIdx.x * 128;
    const int K = 1024, N = 1024;

    const uint32_t as_base = (uint32_t)__cvta_generic_to_shared(As);
    const uint32_t bs_base = (uint32_t)__cvta_generic_to_shared(Bs);

    // stage: 128 rows x 64 halves (8 x 16B chunks per row)
    auto load_stage = [&](int s, int kt) {
        #pragma unroll
        for (int i = 0; i < 4; i++) {
            int id = tid + i * 256;
            int r = id >> 3, ch = id & 7;
            cp_async16(as_base + (s * 128 * 36 + r * 36 + ch * 4) * 4,
                       &A[(size_t)(m0 + r) * K + kt + ch * 8]);
            cp_async16(bs_base + (s * 128 * 36 + r * 36 + ch * 4) * 4,
                       &Bw[(size_t)(n0 + r) * K + kt + ch * 8]);
        }
        cp_commit();
    };

    float acc[2][8][4];
    #pragma unroll
    for (int i = 0; i < 2; i++)
        #pragma unroll
        for (int j = 0; j < 8; j++)
            #pragma unroll
            for (int t = 0; t < 4; t++) acc[i][j][t] = 0.0f;

    load_stage(0, 0);

    int st = 0;
    for (int kt = 0; kt < K; kt += 64, st ^= 1) {
        if (kt + 64 < K) { load_stage(st ^ 1, kt + 64); cp_wait<1>(); }
        else             { cp_wait<0>(); }
        __syncthreads();

        const uint32_t* Ac = As + st * 128 * 36;
        const uint32_t* Bc = Bs + st * 128 * 36;

        #pragma unroll
        for (int c = 0; c < 4; c++) {        // k16 chunks
            const int kc = c * 8;
            uint32_t af[2][4];
            #pragma unroll
            for (int mf = 0; mf < 2; mf++) {
                int r = wm * 32 + mf * 16 + lr;
                af[mf][0] = Ac[r * 36 + kc + lc];
                af[mf][1] = Ac[(r + 8) * 36 + kc + lc];
                af[mf][2] = Ac[r * 36 + kc + lc + 4];
                af[mf][3] = Ac[(r + 8) * 36 + kc + lc + 4];
            }
            uint32_t bf[8][2];
            #pragma unroll
            for (int nf = 0; nf < 8; nf++) {
                int n = wn * 64 + nf * 8 + lr;
                bf[nf][0] = Bc[n * 36 + kc + lc];
                bf[nf][1] = Bc[n * 36 + kc + lc + 4];
            }
            #pragma unroll
            for (int mf = 0; mf < 2; mf++)
                #pragma unroll
                for (int nf = 0; nf < 8; nf++)
                    mma_f16(acc[mf][nf], af[mf], bf[nf]);
        }
        __syncthreads();
    }

    #pragma unroll
    for (int mf = 0; mf < 2; mf++) {
        int r = m0 + wm * 32 + mf * 16 + lr;
        #pragma unroll
        for (int nf = 0; nf < 8; nf++) {
            int c = n0 + wn * 64 + nf * 8 + 2 * lc;
            if (half_out) {
                __half* C = (__half*)Cout;
                *(uint32_t*)&C[(size_t)r * N + c]       = packh2(acc[mf][nf][0], acc[mf][nf][1]);
                *(uint32_t*)&C[(size_t)(r + 8) * N + c] = packh2(acc[mf][nf][2], acc[mf][nf][3]);
            } else {
                float* C = (float*)Cout;
                float b0 = bias ? bias[c] : 0.0f;
                float b1 = bias ? bias[c + 1] : 0.0f;
                float2 v0 = { acc[mf][nf][0] + b0, acc[mf][nf][1] + b1 };
                float2 v1 = { acc[mf][nf][2] + b0, acc[mf][nf][3] + b1 };
                *(float2*)&C[(size_t)r * N + c] = v0;
                *(float2*)&C[(size_t)(r + 8) * N + c] = v1;
            }
        }
    }
}

__global__ __launch_bounds__(256, 2) void gemm_qkv(
    const __half* __restrict__ Xq, const __half* __restrict__ Xk,
    const __half* __restrict__ Xv,
    const __half* __restrict__ Wq, const __half* __restrict__ Wk,
    const __half* __restrict__ Wv,
    __half* __restrict__ Oq, __half* __restrict__ Ok, __half* __restrict__ Ov)
{
    const int z = blockIdx.z;
    const __half* A  = (z == 0) ? Xq : (z == 1) ? Xk : Xv;
    const __half* Bw = (z == 0) ? Wq : (z == 1) ? Wk : Wv;
    __half*       C  = (z == 0) ? Oq : (z == 1) ? Ok : Ov;
    gemm_body_f16(A, Bw, nullptr, C, 1);
}

__global__ __launch_bounds__(256, 2) void gemm_out(
    const __half* __restrict__ A, const __half* __restrict__ Bw,
    const float* __restrict__ bias, float* __restrict__ C)
{
    gemm_body_f16(A, Bw, bias, C, 0);
}

// ======================================================================
// Flash attention fp16 (m16n8k16): 128-q tile, 4 warps (32q each),
// 64-key tiles, register K/V prefetch, warp-local softmax.
// P stays in registers (C-frag of QK packs directly into A-frag of PV).
// V stored TRANSPOSED in smem (dim-major, key pairs as half2).
// smem uint32: qs 128x36 @0, ks 64x36 @4608, vs_t 64x36 @6912
//   total 9216 uint32 = 36,864 B
// ======================================================================
#define FL_SMEM_BYTES (9216 * 4)

__global__ __launch_bounds__(128, 2) void flash_f16(
    const __half* __restrict__ Q, const __half* __restrict__ Kp,
    const __half* __restrict__ Vp, __half* __restrict__ O)
{
    extern __shared__ uint32_t smu[];
    uint32_t* qs = smu;            // [128][36]
    uint32_t* ks = smu + 4608;     // [64][36]
    uint32_t* vt = smu + 6912;     // [64 dims][36] (key pairs)
    __half*  vth = (__half*)vt;    // half view, stride 72 halves per dim-row

    const int tid  = threadIdx.x;
    const int lane = tid & 31;
    const int w    = tid >> 5;
    const int lr   = lane >> 2;
    const int lc   = lane & 3;

    const int bh = blockIdx.y;
    const int b  = bh >> 4;
    const int h  = bh & 15;
    const int q0 = blockIdx.x * 128;

    const int fr  = tid >> 4;          // 0..7
    const int fc4 = tid & 15;          // 0..15 (4-half groups)

    const __half2 sc2 = __float2half2_rn(0.03125f);  // 1/sqrt(1024), exact

    // ---- Q tile (128 x 64 halves), scaled ----
    const __half* qbase = Q + ((size_t)(b * SS + q0)) * DD + h * HD;
    #pragma unroll
    for (int i = 0; i < 16; i++) {
        int r = fr + i * 8;
        uint2 u = *(const uint2*)&qbase[(size_t)r * DD + fc4 * 4];
        __half2 h0 = __hmul2(*(__half2*)&u.x, sc2);
        __half2 h1 = __hmul2(*(__half2*)&u.y, sc2);
        uint2 o = { *(uint32_t*)&h0, *(uint32_t*)&h1 };
        *(uint2*)&qs[r * 36 + fc4 * 2] = o;
    }

    float m_state[2][2], l_state[2][2];
    float acco[2][8][4];
    #pragma unroll
    for (int mf = 0; mf < 2; mf++)
        #pragma unroll
        for (int hh = 0; hh < 2; hh++) { m_state[mf][hh] = -INFINITY; l_state[mf][hh] = 0.0f; }
    #pragma unroll
    for (int mf = 0; mf < 2; mf++)
        #pragma unroll
        for (int nf = 0; nf < 8; nf++)
            #pragma unroll
            for (int t = 0; t < 4; t++) acco[mf][nf][t] = 0.0f;

    // prefetch K/V tile 0
    const __half* kb0 = Kp + ((size_t)(b * SS)) * DD + h * HD;
    const __half* vb0 = Vp + ((size_t)(b * SS)) * DD + h * HD;
    uint2 kreg[8], vreg[8];
    #pragma unroll
    for (int i = 0; i < 8; i++) {
        int r = fr + i * 8;
        kreg[i] = *(const uint2*)&kb0[(size_t)r * DD + fc4 * 4];
        vreg[i] = *(const uint2*)&vb0[(size_t)r * DD + fc4 * 4];
    }

    for (int kb = 0; kb < SS / 64; kb++) {
        __syncthreads();   // previous tile consumed
        #pragma unroll
        for (int i = 0; i < 8; i++) {
            int r = fr + i * 8;                 // key index
            *(uint2*)&ks[r * 36 + fc4 * 2] = kreg[i];
            // V transposed: halves (dims fc4*4..+3, key r)
            uint32_t lo = vreg[i].x, hi = vreg[i].y;
            int d0 = fc4 * 4;
            vth[(d0 + 0) * 72 + r] = __ushort_as_half((unsigned short)(lo & 0xffff));
            vth[(d0 + 1) * 72 + r] = __ushort_as_half((unsigned short)(lo >> 16));
            vth[(d0 + 2) * 72 + r] = __ushort_as_half((unsigned short)(hi & 0xffff));
            vth[(d0 + 3) * 72 + r] = __ushort_as_half((unsigned short)(hi >> 16));
        }
        __syncthreads();   // tile visible

        // prefetch next tile
        if (kb + 1 < SS / 64) {
            const __half* kbn = Kp + ((size_t)(b * SS + (kb + 1) * 64)) * DD + h * HD;
            const __half* vbn = Vp + ((size_t)(b * SS + (kb + 1) * 64)) * DD + h * HD;
            #pragma unroll
            for (int i = 0; i < 8; i++) {
                int r = fr + i * 8;
                kreg[i] = *(const uint2*)&kbn[(size_t)r * DD + fc4 * 4];
                vreg[i] = *(const uint2*)&vbn[(size_t)r * DD + fc4 * 4];
            }
        }

        // ---- S = Q K^T : 32q x 64keys, hd=64 as 4 k16 chunks ----
        float accs[2][8][4];
        #pragma unroll
        for (int mf = 0; mf < 2; mf++)
            #pragma unroll
            for (int nf = 0; nf < 8; nf++)
                #pragma unroll
                for (int t = 0; t < 4; t++) accs[mf][nf][t] = 0.0f;

        #pragma unroll
        for (int c = 0; c < 4; c++) {
            const int kc = c * 8;
            uint32_t af[2][4];
            #pragma unroll
            for (int mf = 0; mf < 2; mf++) {
                int r = w * 32 + mf * 16 + lr;
                af[mf][0] = qs[r * 36 + kc + lc];
                af[mf][1] = qs[(r + 8) * 36 + kc + lc];
                af[mf][2] = qs[r * 36 + kc + lc + 4];
                af[mf][3] = qs[(r + 8) * 36 + kc + lc + 4];
            }
            uint32_t bf[8][2];
            #pragma unroll
            for (int nf = 0; nf < 8; nf++) {
                int n = nf * 8 + lr;           // key
                bf[nf][0] = ks[n * 36 + kc + lc];
                bf[nf][1] = ks[n * 36 + kc + lc + 4];
            }
            #pragma unroll
            for (int mf = 0; mf < 2; mf++)
                #pragma unroll
                for (int nf = 0; nf < 8; nf++)
                    mma_f16(accs[mf][nf], af[mf], bf[nf]);
        }

        // ---- warp-local online softmax ----
        float cc[2][2];
        #pragma unroll
        for (int mf = 0; mf < 2; mf++)
            #pragma unroll
            for (int hh = 0; hh < 2; hh++) {
                float v = -INFINITY;
                #pragma unroll
                for (int nf = 0; nf < 8; nf++) {
                    v = fmaxf(v, accs[mf][nf][2 * hh]);
                    v = fmaxf(v, accs[mf][nf][2 * hh + 1]);
                }
                v = fmaxf(v, __shfl_xor_sync(0xffffffffu, v, 1));
                v = fmaxf(v, __shfl_xor_sync(0xffffffffu, v, 2));
                float mnew = fmaxf(m_state[mf][hh], v);
                cc[mf][hh] = __expf(m_state[mf][hh] - mnew);
                m_state[mf][hh] = mnew;
            }

        float rsum[2][2] = {};
        #pragma unroll
        for (int mf = 0; mf < 2; mf++)
            #pragma unroll
            for (int nf = 0; nf < 8; nf++) {
                float p0 = __expf(accs[mf][nf][0] - m_state[mf][0]);
                float p1 = __expf(accs[mf][nf][1] - m_state[mf][0]);
                float p2 = __expf(accs[mf][nf][2] - m_state[mf][1]);
                float p3 = __expf(accs[mf][nf][3] - m_state[mf][1]);
                accs[mf][nf][0] = p0; accs[mf][nf][1] = p1;
                accs[mf][nf][2] = p2; accs[mf][nf][3] = p3;
                rsum[mf][0] += p0 + p1;
                rsum[mf][1] += p2 + p3;
            }
        #pragma unroll
        for (int mf = 0; mf < 2; mf++)
            #pragma unroll
            for (int hh = 0; hh < 2; hh++) {
                float v = rsum[mf][hh];
                v += __shfl_xor_sync(0xffffffffu, v, 1);
                v += __shfl_xor_sync(0xffffffffu, v, 2);
                l_state[mf][hh] = l_state[mf][hh] * cc[mf][hh] + v;
            }

        #pragma unroll
        for (int mf = 0; mf < 2; mf++)
            #pragma unroll
            for (int nf = 0; nf < 8; nf++) {
                acco[mf][nf][0] *= cc[mf][0];
                acco[mf][nf][1] *= cc[mf][0];
                acco[mf][nf][2] *= cc[mf][1];
                acco[mf][nf][3] *= cc[mf][1];
            }

        // ---- O += P V : P from registers, V^T from smem; 4 k16 chunks ----
        #pragma unroll
        for (int c = 0; c < 4; c++) {
            uint32_t af[2][4];
            #pragma unroll
            for (int mf = 0; mf < 2; mf++) {
                af[mf][0] = packh2(accs[mf][2 * c][0],     accs[mf][2 * c][1]);
                af[mf][1] = packh2(accs[mf][2 * c][2],     accs[mf][2 * c][3]);
                af[mf][2] = packh2(accs[mf][2 * c + 1][0], accs[mf][2 * c + 1][1]);
                af[mf][3] = packh2(accs[mf][2 * c + 1][2], accs[mf][2 * c + 1][3]);
            }
            uint32_t bf[8][2];
            #pragma unroll
            for (int nf = 0; nf < 8; nf++) {
                int n = nf * 8 + lr;           // dim
                bf[nf][0] = vt[n * 36 + c * 8 + lc];
                bf[nf][1] = vt[n * 36 + c * 8 + lc + 4];
            }
            #pragma unroll
            for (int mf = 0; mf < 2; mf++)
                #pragma unroll
                for (int nf = 0; nf < 8; nf++)
                    mma_f16(acco[mf][nf], af[mf], bf[nf]);
        }
    }

    // ---- epilogue: normalize, store half ----
    __half* obase = O + ((size_t)(b * SS + q0)) * DD + h * HD;
    #pragma unroll
    for (int mf = 0; mf < 2; mf++) {
        float inv0 = 1.0f / l_state[mf][0];
        float inv1 = 1.0f / l_state[mf][1];
        int r = w * 32 + mf * 16 + lr;
        #pragma unroll
        for (int nf = 0; nf < 8; nf++) {
            int c = nf * 8 + 2 * lc;
            *(uint32_t*)&obase[(size_t)r * DD + c] =
                packh2(acco[mf][nf][0] * inv0, acco[mf][nf][1] * inv0);
            *(uint32_t*)&obase[(size_t)(r + 8) * DD + c] =
                packh2(acco[mf][nf][2] * inv1, acco[mf][nf][3] * inv1);
        }
    }
}

// ======================================================================
// launch
// ======================================================================
extern "C" void kernel_launch(void* const* d_in, const int* in_sizes, int n_in,
                              void* d_out, int out_size)
{
    const float* queries = (const float*)d_in[0];
    const float* keys    = (const float*)d_in[1];
    const float* values  = (const float*)d_in[2];
    const float* Wq      = (const float*)d_in[3];
    const float* Wk      = (const float*)d_in[4];
    const float* Wv      = (const float*)d_in[5];
    const float* Wo      = (const float*)d_in[6];
    const float* bo      = (const float*)d_in[7];
    float* out = (float*)d_out;

    __half *gqh, *gkh, *gvh, *gwq, *gwk, *gwv, *gwo, *gQp, *gKp, *gVp, *gAh;
    cudaGetSymbolAddress((void**)&gqh, g_qh);
    cudaGetSymbolAddress((void**)&gkh, g_kh);
    cudaGetSymbolAddress((void**)&gvh, g_vh);
    cudaGetSymbolAddress((void**)&gwq, g_wqh);
    cudaGetSymbolAddress((void**)&gwk, g_wkh);
    cudaGetSymbolAddress((void**)&gwv, g_wvh);
    cudaGetSymbolAddress((void**)&gwo, g_woh);
    cudaGetSymbolAddress((void**)&gQp, g_Qp);
    cudaGetSymbolAddress((void**)&gKp, g_Kp);
    cudaGetSymbolAddress((void**)&gVp, g_Vp);
    cudaGetSymbolAddress((void**)&gAh, g_Ah);

    cudaFuncSetAttribute(gemm_qkv,
                         cudaFuncAttributeMaxDynamicSharedMemorySize, G_SMEM_BYTES);
    cudaFuncSetAttribute(gemm_out,
                         cudaFuncAttributeMaxDynamicSharedMemorySize, G_SMEM_BYTES);
    cudaFuncSetAttribute(flash_f16,
                         cudaFuncAttributeMaxDynamicSharedMemorySize, FL_SMEM_BYTES);

    const int NELEM = BB * SS * DD;   // 4M
    const int WELEM = DD * DD;        // 1M

    // fp32 -> fp16 (2 fused launches)
    dim3 ci_grid(NELEM / 4 / 256, 1, 3);
    cvt_in3<<<ci_grid, 256>>>(queries, keys, values, gqh, gkh, gvh, NELEM / 4);
    dim3 cw_grid(WELEM / 4 / 256, 1, 4);
    cvt_w4<<<cw_grid, 256>>>(Wq, Wk, Wv, Wo, gwq, gwk, gwv, gwo, WELEM / 4);

    dim3 qkv_grid(8, 32, 3);   // 768 CTAs
    dim3 gemm_block(256);
    gemm_qkv<<<qkv_grid, gemm_block, G_SMEM_BYTES>>>(
        gqh, gkh, gvh, gwq, gwk, gwv, gQp, gKp, gVp);

    dim3 fl_grid(SS / 128, BB * HH);   // 512 CTAs
    flash_f16<<<fl_grid, 128, FL_SMEM_BYTES>>>(gQp, gKp, gVp, gAh);

    dim3 out_grid(8, 32, 1);
    gemm_out<<<out_grid, gemm_block, G_SMEM_BYTES>>>(gAh, gwo, bo, out);
}

// round 15
// speedup vs baseline: 1.9862x; 1.2221x over previous
#include <cuda_runtime.h>
#include <cuda_fp16.h>
#include <math.h>
#include <stdint.h>

#define BB 2
#define SS 2048
#define DD 1024
#define HH 16
#define HD 64

// -------- scratch (allocation-free: __device__ globals) --------
__device__ __half g_qh[BB*SS*DD];
__device__ __half g_kh[BB*SS*DD];
__device__ __half g_vh[BB*SS*DD];
__device__ __half g_wqh[DD*DD];
__device__ __half g_wkh[DD*DD];
__device__ __half g_wvh[DD*DD];
__device__ __half g_woh[DD*DD];
__device__ __half g_Qp[BB*SS*DD];
__device__ __half g_Kp[BB*SS*DD];
__device__ __half g_Vp[BB*SS*DD];
__device__ __half g_Ah[BB*SS*DD];

// -------- helpers --------
__device__ __forceinline__ void mma_f16(float* d, const uint32_t* a, const uint32_t* b) {
    asm volatile(
        "mma.sync.aligned.m16n8k16.row.col.f32.f16.f16.f32 "
        "{%0,%1,%2,%3},{%4,%5,%6,%7},{%8,%9},{%0,%1,%2,%3};"
        : "+f"(d[0]), "+f"(d[1]), "+f"(d[2]), "+f"(d[3])
        : "r"(a[0]), "r"(a[1]), "r"(a[2]), "r"(a[3]), "r"(b[0]), "r"(b[1]));
}

__device__ __forceinline__ uint32_t packh2(float a, float b) {
    __half2 h = __floats2half2_rn(a, b);
    return *(uint32_t*)&h;
}

__device__ __forceinline__ void ldm_x4(
    uint32_t& r0, uint32_t& r1, uint32_t& r2, uint32_t& r3, uint32_t addr)
{
    asm volatile("ldmatrix.sync.aligned.m8n8.x4.shared.b16 {%0,%1,%2,%3}, [%4];"
                 : "=r"(r0), "=r"(r1), "=r"(r2), "=r"(r3) : "r"(addr));
}
__device__ __forceinline__ void ldm_x4_t(
    uint32_t& r0, uint32_t& r1, uint32_t& r2, uint32_t& r3, uint32_t addr)
{
    asm volatile("ldmatrix.sync.aligned.m8n8.x4.trans.shared.b16 {%0,%1,%2,%3}, [%4];"
                 : "=r"(r0), "=r"(r1), "=r"(r2), "=r"(r3) : "r"(addr));
}

__device__ __forceinline__ void cp_async16(uint32_t smem_addr, const void* gptr) {
    asm volatile("cp.async.cg.shared.global [%0], [%1], 16;"
                 :: "r"(smem_addr), "l"(gptr));
}
__device__ __forceinline__ void cp_commit() {
    asm volatile("cp.async.commit_group;");
}
template <int N>
__device__ __forceinline__ void cp_wait() {
    asm volatile("cp.async.wait_group %0;" :: "n"(N));
}

// ======================================================================
// fp32 -> fp16 conversion passes (fused via grid.z)
// ======================================================================
__global__ __launch_bounds__(256) void cvt_in3(
    const float* __restrict__ a, const float* __restrict__ b, const float* __restrict__ c,
    __half* __restrict__ oa, __half* __restrict__ ob, __half* __restrict__ oc, int n4)
{
    const float* in = (blockIdx.z == 0) ? a : (blockIdx.z == 1) ? b : c;
    __half* out     = (blockIdx.z == 0) ? oa : (blockIdx.z == 1) ? ob : oc;
    int i = blockIdx.x * blockDim.x + threadIdx.x;
    if (i < n4) {
        float4 v = ((const float4*)in)[i];
        uint2 u = { packh2(v.x, v.y), packh2(v.z, v.w) };
        ((uint2*)out)[i] = u;
    }
}

__global__ __launch_bounds__(256) void cvt_w4(
    const float* __restrict__ a, const float* __restrict__ b,
    const float* __restrict__ c, const float* __restrict__ d,
    __half* __restrict__ oa, __half* __restrict__ ob,
    __half* __restrict__ oc, __half* __restrict__ od, int n4)
{
    const float* in = (blockIdx.z == 0) ? a : (blockIdx.z == 1) ? b : (blockIdx.z == 2) ? c : d;
    __half* out     = (blockIdx.z == 0) ? oa : (blockIdx.z == 1) ? ob : (blockIdx.z == 2) ? oc : od;
    int i = blockIdx.x * blockDim.x + threadIdx.x;
    if (i < n4) {
        float4 v = ((const float4*)in)[i];
        uint2 u = { packh2(v.x, v.y), packh2(v.z, v.w) };
        ((uint2*)out)[i] = u;
    }
}

// ======================================================================
// GEMM fp16 (R14-proven): C[M,1024] = A * Bw^T (+bias)
// block 128x128, 256 thr (8 warps 4Mx2N), warp tile 32x64, KT=64 halves
// ======================================================================
#define G_SMEM_BYTES ((2*128*36 + 2*128*36) * 4)

__device__ __forceinline__ void gemm_body_f16(
    const __half* __restrict__ A, const __half* __restrict__ Bw,
    const float* __restrict__ bias, void* Cout, int half_out)
{
    extern __shared__ uint32_t gsm[];
    uint32_t* As = gsm;
    uint32_t* Bs = gsm + 2 * 128 * 36;

    const int tid  = threadIdx.x;
    const int lane = tid & 31;
    const int w    = tid >> 5;
    const int wm   = w & 3;
    const int wn   = w >> 2;
    const int lr   = lane >> 2;
    const int lc   = lane & 3;

    const int m0 = blockIdx.y * 128;
    const int n0 = blockIdx.x * 128;
    const int K = 1024, N = 1024;

    const uint32_t as_base = (uint32_t)__cvta_generic_to_shared(As);
    const uint32_t bs_base = (uint32_t)__cvta_generic_to_shared(Bs);

    auto load_stage = [&](int s, int kt) {
        #pragma unroll
        for (int i = 0; i < 4; i++) {
            int id = tid + i * 256;
            int r = id >> 3, ch = id & 7;
            cp_async16(as_base + (s * 128 * 36 + r * 36 + ch * 4) * 4,
                       &A[(size_t)(m0 + r) * K + kt + ch * 8]);
            cp_async16(bs_base + (s * 128 * 36 + r * 36 + ch * 4) * 4,
                       &Bw[(size_t)(n0 + r) * K + kt + ch * 8]);
        }
        cp_commit();
    };

    float acc[2][8][4];
    #pragma unroll
    for (int i = 0; i < 2; i++)
        #pragma unroll
        for (int j = 0; j < 8; j++)
            #pragma unroll
            for (int t = 0; t < 4; t++) acc[i][j][t] = 0.0f;

    load_stage(0, 0);

    int st = 0;
    for (int kt = 0; kt < K; kt += 64, st ^= 1) {
        if (kt + 64 < K) { load_stage(st ^ 1, kt + 64); cp_wait<1>(); }
        else             { cp_wait<0>(); }
        __syncthreads();

        const uint32_t* Ac = As + st * 128 * 36;
        const uint32_t* Bc = Bs + st * 128 * 36;

        #pragma unroll
        for (int c = 0; c < 4; c++) {
            const int kc = c * 8;
            uint32_t af[2][4];
            #pragma unroll
            for (int mf = 0; mf < 2; mf++) {
                int r = wm * 32 + mf * 16 + lr;
                af[mf][0] = Ac[r * 36 + kc + lc];
                af[mf][1] = Ac[(r + 8) * 36 + kc + lc];
                af[mf][2] = Ac[r * 36 + kc + lc + 4];
                af[mf][3] = Ac[(r + 8) * 36 + kc + lc + 4];
            }
            uint32_t bf[8][2];
            #pragma unroll
            for (int nf = 0; nf < 8; nf++) {
                int n = wn * 64 + nf * 8 + lr;
                bf[nf][0] = Bc[n * 36 + kc + lc];
                bf[nf][1] = Bc[n * 36 + kc + lc + 4];
            }
            #pragma unroll
            for (int mf = 0; mf < 2; mf++)
                #pragma unroll
                for (int nf = 0; nf < 8; nf++)
                    mma_f16(acc[mf][nf], af[mf], bf[nf]);
        }
        __syncthreads();
    }

    #pragma unroll
    for (int mf = 0; mf < 2; mf++) {
        int r = m0 + wm * 32 + mf * 16 + lr;
        #pragma unroll
        for (int nf = 0; nf < 8; nf++) {
            int c = n0 + wn * 64 + nf * 8 + 2 * lc;
            if (half_out) {
                __half* C = (__half*)Cout;
                *(uint32_t*)&C[(size_t)r * N + c]       = packh2(acc[mf][nf][0], acc[mf][nf][1]);
                *(uint32_t*)&C[(size_t)(r + 8) * N + c] = packh2(acc[mf][nf][2], acc[mf][nf][3]);
            } else {
                float* C = (float*)Cout;
                float b0 = bias ? bias[c] : 0.0f;
                float b1 = bias ? bias[c + 1] : 0.0f;
                float2 v0 = { acc[mf][nf][0] + b0, acc[mf][nf][1] + b1 };
                float2 v1 = { acc[mf][nf][2] + b0, acc[mf][nf][3] + b1 };
                *(float2*)&C[(size_t)r * N + c] = v0;
                *(float2*)&C[(size_t)(r + 8) * N + c] = v1;
            }
        }
    }
}

__global__ __launch_bounds__(256, 2) void gemm_qkv(
    const __half* __restrict__ Xq, const __half* __restrict__ Xk,
    const __half* __restrict__ Xv,
    const __half* __restrict__ Wq, const __half* __restrict__ Wk,
    const __half* __restrict__ Wv,
    __half* __restrict__ Oq, __half* __restrict__ Ok, __half* __restrict__ Ov)
{
    const int z = blockIdx.z;
    const __half* A  = (z == 0) ? Xq : (z == 1) ? Xk : Xv;
    const __half* Bw = (z == 0) ? Wq : (z == 1) ? Wk : Wv;
    __half*       C  = (z == 0) ? Oq : (z == 1) ? Ok : Ov;
    gemm_body_f16(A, Bw, nullptr, C, 1);
}

__global__ __launch_bounds__(256, 2) void gemm_out(
    const __half* __restrict__ A, const __half* __restrict__ Bw,
    const float* __restrict__ bias, float* __restrict__ C)
{
    gemm_body_f16(A, Bw, bias, C, 0);
}

// ======================================================================
// Flash attention fp16 v2: ldmatrix for all smem fragment traffic.
// 128-q tile, 4 warps (32q each), 64-key tiles, register K/V prefetch,
// warp-local softmax, P in registers. Q/K/V all row-major in smem,
// stride 36 uint32 (144B rows -> ldmatrix conflict-free).
// smem uint32: qs 128x36 @0, ks 64x36 @4608, vs 64x36 @6912 -> 36,864 B
// ======================================================================
#define FL_SMEM_BYTES (9216 * 4)

__global__ __launch_bounds__(128, 2) void flash_f16(
    const __half* __restrict__ Q, const __half* __restrict__ Kp,
    const __half* __restrict__ Vp, __half* __restrict__ O)
{
    extern __shared__ uint32_t smu[];
    uint32_t* qs = smu;            // [128][36]
    uint32_t* ks = smu + 4608;     // [64][36]
    uint32_t* vs = smu + 6912;     // [64][36]

    const int tid  = threadIdx.x;
    const int lane = tid & 31;
    const int w    = tid >> 5;
    const int lr   = lane >> 2;
    const int lc   = lane & 3;

    const int bh = blockIdx.y;
    const int b  = bh >> 4;
    const int h  = bh & 15;
    const int q0 = blockIdx.x * 128;

    const int fr  = tid >> 4;          // 0..7
    const int fc4 = tid & 15;          // 0..15

    const __half2 sc2 = __float2half2_rn(0.03125f);  // 1/sqrt(1024)

    const uint32_t qs_b = (uint32_t)__cvta_generic_to_shared(qs);
    const uint32_t ks_b = (uint32_t)__cvta_generic_to_shared(ks);
    const uint32_t vs_b = (uint32_t)__cvta_generic_to_shared(vs);

    // per-lane ldmatrix base addresses (byte offsets)
    // A/V pattern: row = (l&7) + 8*((l>>3)&1), colsel = (l>>4)&1
    // K pattern:   row = (l&7) + 8*((l>>4)&1), colsel = (l>>3)&1
    const int rowA = (lane & 7) + 8 * ((lane >> 3) & 1);
    const int selA = (lane >> 4) & 1;
    const int rowK = (lane & 7) + 8 * ((lane >> 4) & 1);
    const int selK = (lane >> 3) & 1;
    const uint32_t qA = qs_b + (uint32_t)((w * 32 + rowA) * 144 + selA * 16);
    const uint32_t kB = ks_b + (uint32_t)(rowK * 144 + selK * 16);
    const uint32_t vB = vs_b + (uint32_t)(rowA * 144 + selA * 16);

    // ---- Q tile (128 x 64 halves), scaled, row-major ----
    const __half* qbase = Q + ((size_t)(b * SS + q0)) * DD + h * HD;
    #pragma unroll
    for (int i = 0; i < 16; i++) {
        int r = fr + i * 8;
        uint2 u = *(const uint2*)&qbase[(size_t)r * DD + fc4 * 4];
        __half2 h0 = __hmul2(*(__half2*)&u.x, sc2);
        __half2 h1 = __hmul2(*(__half2*)&u.y, sc2);
        uint2 o = { *(uint32_t*)&h0, *(uint32_t*)&h1 };
        *(uint2*)&qs[r * 36 + fc4 * 2] = o;
    }

    float m_state[2][2], l_state[2][2];
    float acco[2][8][4];
    #pragma unroll
    for (int mf = 0; mf < 2; mf++)
        #pragma unroll
        for (int hh = 0; hh < 2; hh++) { m_state[mf][hh] = -INFINITY; l_state[mf][hh] = 0.0f; }
    #pragma unroll
    for (int mf = 0; mf < 2; mf++)
        #pragma unroll
        for (int nf = 0; nf < 8; nf++)
            #pragma unroll
            for (int t = 0; t < 4; t++) acco[mf][nf][t] = 0.0f;

    // prefetch K/V tile 0
    const __half* kb0 = Kp + ((size_t)(b * SS)) * DD + h * HD;
    const __half* vb0 = Vp + ((size_t)(b * SS)) * DD + h * HD;
    uint2 kreg[8], vreg[8];
    #pragma unroll
    for (int i = 0; i < 8; i++) {
        int r = fr + i * 8;
        kreg[i] = *(const uint2*)&kb0[(size_t)r * DD + fc4 * 4];
        vreg[i] = *(const uint2*)&vb0[(size_t)r * DD + fc4 * 4];
    }

    for (int kb = 0; kb < SS / 64; kb++) {
        __syncthreads();
        #pragma unroll
        for (int i = 0; i < 8; i++) {
            int r = fr + i * 8;
            *(uint2*)&ks[r * 36 + fc4 * 2] = kreg[i];
            *(uint2*)&vs[r * 36 + fc4 * 2] = vreg[i];
        }
        __syncthreads();

        if (kb + 1 < SS / 64) {
            const __half* kbn = Kp + ((size_t)(b * SS + (kb + 1) * 64)) * DD + h * HD;
            const __half* vbn = Vp + ((size_t)(b * SS + (kb + 1) * 64)) * DD + h * HD;
            #pragma unroll
            for (int i = 0; i < 8; i++) {
                int r = fr + i * 8;
                kreg[i] = *(const uint2*)&kbn[(size_t)r * DD + fc4 * 4];
                vreg[i] = *(const uint2*)&vbn[(size_t)r * DD + fc4 * 4];
            }
        }

        // ---- S = Q K^T : 32q x 64keys, 4 k16 chunks (ldmatrix) ----
        float accs[2][8][4];
        #pragma unroll
        for (int mf = 0; mf < 2; mf++)
            #pragma unroll
            for (int nf = 0; nf < 8; nf++)
                #pragma unroll
                for (int t = 0; t < 4; t++) accs[mf][nf][t] = 0.0f;

        #pragma unroll
        for (int c = 0; c < 4; c++) {
            uint32_t af[2][4];
            #pragma unroll
            for (int mf = 0; mf < 2; mf++)
                ldm_x4(af[mf][0], af[mf][1], af[mf][2], af[mf][3],
                       qA + mf * (16 * 144) + c * 32);
            uint32_t bf[8][2];
            #pragma unroll
            for (int p = 0; p < 4; p++)
                ldm_x4(bf[2*p][0], bf[2*p][1], bf[2*p+1][0], bf[2*p+1][1],
                       kB + p * (16 * 144) + c * 32);
            #pragma unroll
            for (int mf = 0; mf < 2; mf++)
                #pragma unroll
                for (int nf = 0; nf < 8; nf++)
                    mma_f16(accs[mf][nf], af[mf], bf[nf]);
        }

        // ---- warp-local online softmax ----
        float cc[2][2];
        #pragma unroll
        for (int mf = 0; mf < 2; mf++)
            #pragma unroll
            for (int hh = 0; hh < 2; hh++) {
                float v = -INFINITY;
                #pragma unroll
                for (int nf = 0; nf < 8; nf++) {
                    v = fmaxf(v, accs[mf][nf][2 * hh]);
                    v = fmaxf(v, accs[mf][nf][2 * hh + 1]);
                }
                v = fmaxf(v, __shfl_xor_sync(0xffffffffu, v, 1));
                v = fmaxf(v, __shfl_xor_sync(0xffffffffu, v, 2));
                float mnew = fmaxf(m_state[mf][hh], v);
                cc[mf][hh] = __expf(m_state[mf][hh] - mnew);
                m_state[mf][hh] = mnew;
            }

        float rsum[2][2] = {};
        #pragma unroll
        for (int mf = 0; mf < 2; mf++)
            #pragma unroll
            for (int nf = 0; nf < 8; nf++) {
                float p0 = __expf(accs[mf][nf][0] - m_state[mf][0]);
                float p1 = __expf(accs[mf][nf][1] - m_state[mf][0]);
                float p2 = __expf(accs[mf][nf][2] - m_state[mf][1]);
                float p3 = __expf(accs[mf][nf][3] - m_state[mf][1]);
                accs[mf][nf][0] = p0; accs[mf][nf][1] = p1;
                accs[mf][nf][2] = p2; accs[mf][nf][3] = p3;
                rsum[mf][0] += p0 + p1;
                rsum[mf][1] += p2 + p3;
            }
        #pragma unroll
        for (int mf = 0; mf < 2; mf++)
            #pragma unroll
            for (int hh = 0; hh < 2; hh++) {
                float v = rsum[mf][hh];
                v += __shfl_xor_sync(0xffffffffu, v, 1);
                v += __shfl_xor_sync(0xffffffffu, v, 2);
                l_state[mf][hh] = l_state[mf][hh] * cc[mf][hh] + v;
            }

        #pragma unroll
        for (int mf = 0; mf < 2; mf++)
            #pragma unroll
            for (int nf = 0; nf < 8; nf++) {
                acco[mf][nf][0] *= cc[mf][0];
                acco[mf][nf][1] *= cc[mf][0];
                acco[mf][nf][2] *= cc[mf][1];
                acco[mf][nf][3] *= cc[mf][1];
            }

        // ---- O += P V : P regs, V via ldmatrix.trans; 4 k16 chunks ----
        #pragma unroll
        for (int c = 0; c < 4; c++) {
            uint32_t af[2][4];
            #pragma unroll
            for (int mf = 0; mf < 2; mf++) {
                af[mf][0] = packh2(accs[mf][2 * c][0],     accs[mf][2 * c][1]);
                af[mf][1] = packh2(accs[mf][2 * c][2],     accs[mf][2 * c][3]);
                af[mf][2] = packh2(accs[mf][2 * c + 1][0], accs[mf][2 * c + 1][1]);
                af[mf][3] = packh2(accs[mf][2 * c + 1][2], accs[mf][2 * c + 1][3]);
            }
            uint32_t bf[8][2];
            #pragma unroll
            for (int p = 0; p < 4; p++)
                ldm_x4_t(bf[2*p][0], bf[2*p][1], bf[2*p+1][0], bf[2*p+1][1],
                         vB + c * (16 * 144) + p * 32);
            #pragma unroll
            for (int mf = 0; mf < 2; mf++)
                #pragma unroll
                for (int nf = 0; nf < 8; nf++)
                    mma_f16(acco[mf][nf], af[mf], bf[nf]);
        }
    }

    // ---- epilogue: normalize, store half ----
    __half* obase = O + ((size_t)(b * SS + q0)) * DD + h * HD;
    #pragma unroll
    for (int mf = 0; mf < 2; mf++) {
        float inv0 = 1.0f / l_state[mf][0];
        float inv1 = 1.0f / l_state[mf][1];
        int r = w * 32 + mf * 16 + lr;
        #pragma unroll
        for (int nf = 0; nf < 8; nf++) {
            int c = nf * 8 + 2 * lc;
            *(uint32_t*)&obase[(size_t)r * DD + c] =
                packh2(acco[mf][nf][0] * inv0, acco[mf][nf][1] * inv0);
            *(uint32_t*)&obase[(size_t)(r + 8) * DD + c] =
                packh2(acco[mf][nf][2] * inv1, acco[mf][nf][3] * inv1);
        }
    }
}

// ======================================================================
// launch
// ======================================================================
extern "C" void kernel_launch(void* const* d_in, const int* in_sizes, int n_in,
                              void* d_out, int out_size)
{
    const float* queries = (const float*)d_in[0];
    const float* keys    = (const float*)d_in[1];
    const float* values  = (const float*)d_in[2];
    const float* Wq      = (const float*)d_in[3];
    const float* Wk      = (const float*)d_in[4];
    const float* Wv      = (const float*)d_in[5];
    const float* Wo      = (const float*)d_in[6];
    const float* bo      = (const float*)d_in[7];
    float* out = (float*)d_out;

    __half *gqh, *gkh, *gvh, *gwq, *gwk, *gwv, *gwo, *gQp, *gKp, *gVp, *gAh;
    cudaGetSymbolAddress((void**)&gqh, g_qh);
    cudaGetSymbolAddress((void**)&gkh, g_kh);
    cudaGetSymbolAddress((void**)&gvh, g_vh);
    cudaGetSymbolAddress((void**)&gwq, g_wqh);
    cudaGetSymbolAddress((void**)&gwk, g_wkh);
    cudaGetSymbolAddress((void**)&gwv, g_wvh);
    cudaGetSymbolAddress((void**)&gwo, g_woh);
    cudaGetSymbolAddress((void**)&gQp, g_Qp);
    cudaGetSymbolAddress((void**)&gKp, g_Kp);
    cudaGetSymbolAddress((void**)&gVp, g_Vp);
    cudaGetSymbolAddress((void**)&gAh, g_Ah);

    cudaFuncSetAttribute(gemm_qkv,
                         cudaFuncAttributeMaxDynamicSharedMemorySize, G_SMEM_BYTES);
    cudaFuncSetAttribute(gemm_out,
                         cudaFuncAttributeMaxDynamicSharedMemorySize, G_SMEM_BYTES);
    cudaFuncSetAttribute(flash_f16,
                         cudaFuncAttributeMaxDynamicSharedMemorySize, FL_SMEM_BYTES);

    const int NELEM = BB * SS * DD;   // 4M
    const int WELEM = DD * DD;        // 1M

    dim3 ci_grid(NELEM / 4 / 256, 1, 3);
    cvt_in3<<<ci_grid, 256>>>(queries, keys, values, gqh, gkh, gvh, NELEM / 4);
    dim3 cw_grid(WELEM / 4 / 256, 1, 4);
    cvt_w4<<<cw_grid, 256>>>(Wq, Wk, Wv, Wo, gwq, gwk, gwv, gwo, WELEM / 4);

    dim3 qkv_grid(8, 32, 3);   // 768 CTAs
    dim3 gemm_block(256);
    gemm_qkv<<<qkv_grid, gemm_block, G_SMEM_BYTES>>>(
        gqh, gkh, gvh, gwq, gwk, gwv, gQp, gKp, gVp);

    dim3 fl_grid(SS / 128, BB * HH);   // 512 CTAs
    flash_f16<<<fl_grid, 128, FL_SMEM_BYTES>>>(gQp, gKp, gVp, gAh);

    dim3 out_grid(8, 32, 1);
    gemm_out<<<out_grid, gemm_block, G_SMEM_BYTES>>>(gAh, gwo, bo, out);
}